// round 3
// baseline (speedup 1.0000x reference)
#include <cuda_runtime.h>
#include <cuda_bf16.h>
#include <cstdint>

// Problem constants (fixed by the dataset): B=8, S=4096, D=1024, fp32.
#define BB 8
#define SS 4096
#define DD 1024

// Scratch: gather index per (b, j). -1 => output zeros for that row.
__device__ int g_idx[BB * SS];

// ---------------------------------------------------------------------------
// Kernel 1: per-batch inclusive prefix sum of boundary_mask -> gather index.
// One block per batch (8 blocks, 256 threads, 16 elements/thread).
//
// Math note (why the affine scan collapses): at a boundary j, a=0,b=cur so
// y_j = cur_j exactly; within a segment cum (hence cur) is constant, and the
// EMA y = (1-p) y + p cur is at its fixed point y = cur from the segment's
// first element on. Before the first boundary cur = 0 and b = 0, so y = 0.
// Therefore y[b,j,:] = cum>0 ? compressed[b, cum-1, :] : 0  -- a pure gather.
//
// Mask dtype is detected at runtime: harness may materialize the bool mask as
// int32 (1 word/elem) or uint8 (1 byte/elem). Under the byte layout the first
// 8192 words are built from random 0/1 bytes and are essentially never all in
// {0,1}; under the int32 layout they always are.
// ---------------------------------------------------------------------------
__global__ void dechunk_scan_kernel(const void* __restrict__ mask_raw)
{
    const int b    = blockIdx.x;
    const int tid  = threadIdx.x;
    const int PER  = SS / 256;             // 16

    __shared__ int warp_sums[8];

    const unsigned int*  m32 = (const unsigned int*)mask_raw;
    const unsigned char* m8  = (const unsigned char*)mask_raw;

    // --- dtype detection over the first 8192 words (valid either way) ---
    int bad = 0;                            // word not in {0,1} -> byte layout
#pragma unroll
    for (int i = 0; i < 32; ++i) {
        unsigned int w = m32[tid * 32 + i];
        bad |= (w > 1u);
    }
    const int is_byte_layout = __syncthreads_or(bad);

    const int base = b * SS + tid * PER;

    // Local inclusive scan over this thread's 16 elements.
    int local[PER];
    int s = 0;
#pragma unroll
    for (int i = 0; i < PER; ++i) {
        int bit = is_byte_layout ? (m8[base + i] != 0)
                                 : (m32[base + i] != 0u);
        s += bit;
        local[i] = s;
    }

    // Warp inclusive scan of per-thread totals.
    const int lane = tid & 31, warp = tid >> 5;
    int v = s;
#pragma unroll
    for (int o = 1; o < 32; o <<= 1) {
        int t = __shfl_up_sync(0xFFFFFFFFu, v, o);
        if (lane >= o) v += t;
    }
    if (lane == 31) warp_sums[warp] = v;
    __syncthreads();

    // Scan the 8 warp totals in warp 0.
    if (warp == 0) {
        int w = (lane < 8) ? warp_sums[lane] : 0;
#pragma unroll
        for (int o = 1; o < 8; o <<= 1) {
            int t = __shfl_up_sync(0xFFFFFFFFu, w, o);
            if (lane >= o) w += t;
        }
        if (lane < 8) warp_sums[lane] = w;
    }
    __syncthreads();

    // Exclusive prefix for this thread, then write gather indices.
    const int prefix = (v - s) + ((warp > 0) ? warp_sums[warp - 1] : 0);
#pragma unroll
    for (int i = 0; i < PER; ++i) {
        g_idx[base + i] = prefix + local[i] - 1;   // cum-1; -1 when cum==0
    }
}

// ---------------------------------------------------------------------------
// Kernel 2: row gather. One block per (b, j) output row; 256 threads each
// move one float4 (256 * 16B = 4 KB = D floats). Streaming stores keep L2
// for the gather source rows, which are reused across consecutive j.
// ---------------------------------------------------------------------------
__global__ __launch_bounds__(256)
void dechunk_gather_kernel(const float* __restrict__ comp,
                           float* __restrict__ out)
{
    const long long row = blockIdx.x;          // b*S + j
    const int b   = (int)(row >> 12);          // row / 4096
    const int idx = g_idx[row];

    float4* dst = reinterpret_cast<float4*>(out + row * (long long)DD);

    if (idx < 0) {
        __stcs(&dst[threadIdx.x], make_float4(0.f, 0.f, 0.f, 0.f));
    } else {
        const float4* src = reinterpret_cast<const float4*>(
            comp + ((long long)b * SS + idx) * (long long)DD);
        float4 vsrc = __ldg(&src[threadIdx.x]);
        __stcs(&dst[threadIdx.x], vsrc);
    }
}

// ---------------------------------------------------------------------------
// Launch. Inputs identified by element count (order-proof):
//   compressed_states fp32 [8,4096,1024] -> 33554432 elems
//   boundary_prob     fp32 [8,4096,2]    ->    65536 elems (unused)
//   boundary_mask     bool [8,4096]      ->    32768 elems
// Output: fp32 [8,4096,1024]
// ---------------------------------------------------------------------------
extern "C" void kernel_launch(void* const* d_in, const int* in_sizes, int n_in,
                              void* d_out, int out_size)
{
    const void* comp_p = d_in[0];
    const void* mask_p = (n_in > 2) ? d_in[2] : d_in[0];

    for (int i = 0; i < n_in; ++i) {
        if (in_sizes[i] == BB * SS * DD) comp_p = d_in[i];
        else if (in_sizes[i] == BB * SS) mask_p = d_in[i];
    }

    const float* comp = (const float*)comp_p;
    float*       out  = (float*)d_out;

    dechunk_scan_kernel<<<BB, 256>>>(mask_p);
    dechunk_gather_kernel<<<BB * SS, 256>>>(comp, out);
}

// round 5
// speedup vs baseline: 1.1989x; 1.1989x over previous
#include <cuda_runtime.h>
#include <cuda_bf16.h>
#include <cstdint>

// Problem constants (fixed by the dataset): B=8, S=4096, D=1024, fp32.
#define BB 8
#define SS 4096
#define DD 1024

// Scratch: gather index per (b, j). -1 => output zeros for that row.
__device__ int g_idx[BB * SS];

// ---------------------------------------------------------------------------
// Kernel 1: per-batch inclusive prefix sum of boundary_mask -> gather index.
// One block per batch (8 blocks, 256 threads, 16 elements/thread).
//
// Math note (why the affine scan collapses): at a boundary j, a=0,b=cur so
// y_j = cur_j exactly; within a segment cum (hence cur) is constant, and the
// EMA y = (1-p) y + p cur sits at its fixed point y = cur from the segment's
// first element on. Before the first boundary cur = 0 and b = 0, so y = 0.
// Therefore y[b,j,:] = cum>0 ? compressed[b, cum-1, :] : 0  -- a pure gather.
//
// Mask dtype detected at runtime (harness materializes bool as int32 here;
// byte fallback kept for robustness).
// ---------------------------------------------------------------------------
__global__ void dechunk_scan_kernel(const void* __restrict__ mask_raw)
{
    const int b    = blockIdx.x;
    const int tid  = threadIdx.x;
    const int PER  = SS / 256;             // 16

    __shared__ int warp_sums[8];

    const unsigned int*  m32 = (const unsigned int*)mask_raw;
    const unsigned char* m8  = (const unsigned char*)mask_raw;

    // dtype detection over the first 8192 words (in-bounds either way)
    int bad = 0;
#pragma unroll
    for (int i = 0; i < 32; ++i) {
        unsigned int w = m32[tid * 32 + i];
        bad |= (w > 1u);
    }
    const int is_byte_layout = __syncthreads_or(bad);

    const int base = b * SS + tid * PER;

    int local[PER];
    int s = 0;
#pragma unroll
    for (int i = 0; i < PER; ++i) {
        int bit = is_byte_layout ? (m8[base + i] != 0)
                                 : (m32[base + i] != 0u);
        s += bit;
        local[i] = s;
    }

    const int lane = tid & 31, warp = tid >> 5;
    int v = s;
#pragma unroll
    for (int o = 1; o < 32; o <<= 1) {
        int t = __shfl_up_sync(0xFFFFFFFFu, v, o);
        if (lane >= o) v += t;
    }
    if (lane == 31) warp_sums[warp] = v;
    __syncthreads();

    if (warp == 0) {
        int w = (lane < 8) ? warp_sums[lane] : 0;
#pragma unroll
        for (int o = 1; o < 8; o <<= 1) {
            int t = __shfl_up_sync(0xFFFFFFFFu, w, o);
            if (lane >= o) w += t;
        }
        if (lane < 8) warp_sums[lane] = w;
    }
    __syncthreads();

    const int prefix = (v - s) + ((warp > 0) ? warp_sums[warp - 1] : 0);
#pragma unroll
    for (int i = 0; i < PER; ++i) {
        g_idx[base + i] = prefix + local[i] - 1;   // cum-1; -1 when cum==0
    }
}

// ---------------------------------------------------------------------------
// Kernel 2: row gather with high MLP.
// 256-thread block covers 8 output rows (8 warps, one warp per row).
// Each thread issues 8 independent LDG.128 (batched) then 8 streaming STG.128.
// Row = 256 float4; warp covers it as 8 coalesced 512B segments.
// ---------------------------------------------------------------------------
__global__ __launch_bounds__(256)
void dechunk_gather_kernel(const float* __restrict__ comp,
                           float* __restrict__ out)
{
    const int warp = threadIdx.x >> 5;           // 0..7 -> row within block
    const int lane = threadIdx.x & 31;

    const int row = blockIdx.x * 8 + warp;       // b*S + j   (< 32768, fits int)
    const int b   = row >> 12;
    const int idx = g_idx[row];

    float4* dst = reinterpret_cast<float4*>(out) + (long long)row * 256;

    if (idx < 0) {
        const float4 z = make_float4(0.f, 0.f, 0.f, 0.f);
#pragma unroll
        for (int i = 0; i < 8; ++i)
            __stcs(&dst[lane + 32 * i], z);
    } else {
        const float4* src = reinterpret_cast<const float4*>(comp)
                          + ((long long)(b * SS + idx)) * 256;
        float4 v[8];
#pragma unroll
        for (int i = 0; i < 8; ++i)              // 8 independent loads -> MLP=8
            v[i] = __ldg(&src[lane + 32 * i]);
#pragma unroll
        for (int i = 0; i < 8; ++i)
            __stcs(&dst[lane + 32 * i], v[i]);
    }
}

// ---------------------------------------------------------------------------
// Launch. Inputs identified by element count (order-proof):
//   compressed_states fp32 [8,4096,1024] -> 33554432 elems
//   boundary_prob     fp32 [8,4096,2]    ->    65536 elems (unused)
//   boundary_mask     bool [8,4096]      ->    32768 elems
// Output: fp32 [8,4096,1024]
// ---------------------------------------------------------------------------
extern "C" void kernel_launch(void* const* d_in, const int* in_sizes, int n_in,
                              void* d_out, int out_size)
{
    const void* comp_p = d_in[0];
    const void* mask_p = (n_in > 2) ? d_in[2] : d_in[0];

    for (int i = 0; i < n_in; ++i) {
        if (in_sizes[i] == BB * SS * DD) comp_p = d_in[i];
        else if (in_sizes[i] == BB * SS) mask_p = d_in[i];
    }

    const float* comp = (const float*)comp_p;
    float*       out  = (float*)d_out;

    dechunk_scan_kernel<<<BB, 256>>>(mask_p);
    dechunk_gather_kernel<<<(BB * SS) / 8, 256>>>(comp, out);
}

// round 7
// speedup vs baseline: 1.4862x; 1.2397x over previous
#include <cuda_runtime.h>
#include <cuda_bf16.h>
#include <cstdint>

// Problem constants (fixed by the dataset): B=8, S=4096, D=1024, fp32.
#define BB 8
#define SS 4096
#define DD 1024

// ---------------------------------------------------------------------------
// Fused kernel: inline mask-prefix + row gather.
//
// Math note (why the affine scan collapses): at a boundary j, a=0,b=cur so
// y_j = cur_j exactly; within a segment cum (hence cur) is constant and the
// EMA y = (1-p) y + p cur sits at its fixed point y = cur from the segment's
// first element on. Before the first boundary, cur = 0 and b = 0, so y = 0.
// Therefore y[b,j,:] = cum>0 ? compressed[b, cum-1, :] : 0  -- a pure gather.
//
// Mask layout: int32 words, one per element (established experimentally:
// byte interpretation fails with rel_err 1.41, int32 passes at 1.9e-8).
//
// Block k (of 4096): batch b = k>>9, rows j0..j0+7 where j0 = (k&511)*8.
// Phase A: 256 threads count mask[b, 0:j0] (coalesced, L2-resident since all
//          blocks share the same 128 KB), block-reduce, thread 0 extends the
//          count through the 8-row window -> per-row gather index in smem.
// Phase B: warp w copies row j0+w: 8 independent LDG.128 (MLP=8), then 8
//          streaming STG.128 (output is write-once; keep L2 for the source).
// ---------------------------------------------------------------------------
__global__ __launch_bounds__(256)
void dechunk_fused_kernel(const float* __restrict__ comp,
                          const unsigned int* __restrict__ mask32,
                          float* __restrict__ out)
{
    const int blk  = blockIdx.x;            // 0..4095
    const int b    = blk >> 9;              // 512 blocks per batch
    const int j0   = (blk & 511) << 3;      // first row of this block's window
    const int tid  = threadIdx.x;
    const int lane = tid & 31;
    const int warp = tid >> 5;

    __shared__ int          warp_sums[8];
    __shared__ int          idx_sh[8];
    __shared__ unsigned int win[8];

    const unsigned int* m = mask32 + b * SS;

    // ---- Phase A: prefix count of boundaries in [0, j0), plus window bits --
    if (tid < 8) win[tid] = m[j0 + tid];

    int s = 0;
    for (int i = tid; i < j0; i += 256)     // <= 16 iterations, coalesced
        s += (m[i] != 0u) ? 1 : 0;

#pragma unroll
    for (int o = 16; o > 0; o >>= 1)
        s += __shfl_down_sync(0xFFFFFFFFu, s, o);
    if (lane == 0) warp_sums[warp] = s;
    __syncthreads();

    if (tid == 0) {
        int cum = 0;
#pragma unroll
        for (int i = 0; i < 8; ++i) cum += warp_sums[i];
#pragma unroll
        for (int i = 0; i < 8; ++i) {
            cum += (win[i] != 0u) ? 1 : 0;
            idx_sh[i] = cum - 1;            // -1 when no boundary seen yet
        }
    }
    __syncthreads();

    // ---- Phase B: row gather (identical to measured 30.7us version) -------
    const int idx = idx_sh[warp];
    const int row = blk * 8 + warp;         // b*SS + j0 + warp

    float4* dst = reinterpret_cast<float4*>(out) + (long long)row * 256;

    if (idx < 0) {
        const float4 z = make_float4(0.f, 0.f, 0.f, 0.f);
#pragma unroll
        for (int i = 0; i < 8; ++i)
            __stcs(&dst[lane + 32 * i], z);
    } else {
        const float4* src = reinterpret_cast<const float4*>(comp)
                          + ((long long)(b * SS + idx)) * 256;
        float4 v[8];
#pragma unroll
        for (int i = 0; i < 8; ++i)         // 8 independent loads -> MLP=8
            v[i] = __ldg(&src[lane + 32 * i]);
#pragma unroll
        for (int i = 0; i < 8; ++i)
            __stcs(&dst[lane + 32 * i], v[i]);
    }
}

// ---------------------------------------------------------------------------
// Launch. Inputs identified by element count (order-proof):
//   compressed_states fp32 [8,4096,1024] -> 33554432 elems
//   boundary_prob     fp32 [8,4096,2]    ->    65536 elems (unused)
//   boundary_mask     bool [8,4096]      ->    32768 elems (int32 words)
// Output: fp32 [8,4096,1024]
// ---------------------------------------------------------------------------
extern "C" void kernel_launch(void* const* d_in, const int* in_sizes, int n_in,
                              void* d_out, int out_size)
{
    const void* comp_p = d_in[0];
    const void* mask_p = (n_in > 2) ? d_in[2] : d_in[0];

    for (int i = 0; i < n_in; ++i) {
        if (in_sizes[i] == BB * SS * DD) comp_p = d_in[i];
        else if (in_sizes[i] == BB * SS) mask_p = d_in[i];
    }

    dechunk_fused_kernel<<<(BB * SS) / 8, 256>>>(
        (const float*)comp_p, (const unsigned int*)mask_p, (float*)d_out);
}